// round 2
// baseline (speedup 1.0000x reference)
#include <cuda_runtime.h>
#include <math_constants.h>
#include <cstdint>
#include <cstddef>

// Problem constants (fixed shapes from reference)
#define K_CODES 8192
#define D_DIM   256
#define T_DIM   2048
#define B_DIM   8
#define N_Q     (B_DIM * T_DIM)          /* 16384 */
#define OUT_SEC (B_DIM * D_DIM * T_DIM)  /* 4194304 */

#define ONE_M_DECAY 0.009999999776482582092285156250f  /* fl32(1-0.99 in f64) */
#define EPS_F 1e-5f
#define FIX_SCALE 4294967296.0   /* 2^32 fixed-point for deterministic sums */

// Device scratch (no allocations allowed)
__device__ float              g_enorm[K_CODES];      // emulated ||e_k||^2 (fp32, XLA order)
__device__ float              g_xnorm[N_Q];          // emulated ||x_n||^2
__device__ int                g_idx[N_Q];
__device__ int                g_cnt[K_CODES];
__device__ unsigned long long g_dw[K_CODES * D_DIM]; // fixed-point 2^32
__device__ float              g_nval;

// ---------------------------------------------------------------------------
// Zero accumulators (every launch: deterministic work)
// ---------------------------------------------------------------------------
__global__ void vq_zero() {
    int i = blockIdx.x * blockDim.x + threadIdx.x;
    int stride = gridDim.x * blockDim.x;
    for (int j = i; j < K_CODES * D_DIM; j += stride) g_dw[j] = 0ull;
    for (int j = i; j < K_CODES; j += stride) g_cnt[j] = 0;
}

// ---------------------------------------------------------------------------
// Emulated XLA-CPU row reduce of squares: 8 strided lane accumulators
// (plain mul then add, NO fma contraction), then horizontal
// ((S0+S4)+(S2+S6)) + ((S1+S5)+(S3+S7)).
// ---------------------------------------------------------------------------
__device__ __forceinline__ float emu_sumsq(const float v[8][D_DIM / 8 > 0 ? 1 : 1],
                                           int dummy);  // unused prototype guard

__device__ __forceinline__ float emu_hreduce(const float S[8]) {
    float t1 = __fadd_rn(S[0], S[4]);
    float t2 = __fadd_rn(S[2], S[6]);
    float t3 = __fadd_rn(S[1], S[5]);
    float t4 = __fadd_rn(S[3], S[7]);
    return __fadd_rn(__fadd_rn(t1, t2), __fadd_rn(t3, t4));
}

// ||e_k||^2: one thread per code row (contiguous 256 floats)
__global__ void vq_bnorm(const float* __restrict__ E) {
    int k = blockIdx.x * blockDim.x + threadIdx.x;
    if (k >= K_CODES) return;
    const float* row = E + (size_t)k * D_DIM;
    float S[8];
#pragma unroll
    for (int j = 0; j < 8; j++) S[j] = 0.0f;
#pragma unroll 4
    for (int i = 0; i < D_DIM / 8; i++) {
#pragma unroll
        for (int j = 0; j < 8; j++) {
            float v = row[i * 8 + j];
            S[j] = __fadd_rn(S[j], __fmul_rn(v, v));
        }
    }
    g_enorm[k] = emu_hreduce(S);
}

// ||x_n||^2: one thread per query; x is [B, D, T] so reads are strided by T
// but coalesced across the warp (consecutive t per lane).
__global__ void vq_anorm(const float* __restrict__ x) {
    int n = blockIdx.x * blockDim.x + threadIdx.x;
    if (n >= N_Q) return;
    int b = n >> 11;
    int t = n & (T_DIM - 1);
    const float* xb = x + (size_t)b * D_DIM * T_DIM + t;
    float S[8];
#pragma unroll
    for (int j = 0; j < 8; j++) S[j] = 0.0f;
#pragma unroll 4
    for (int i = 0; i < D_DIM / 8; i++) {
#pragma unroll
        for (int j = 0; j < 8; j++) {
            float v = xb[(size_t)(i * 8 + j) * T_DIM];
            S[j] = __fadd_rn(S[j], __fmul_rn(v, v));
        }
    }
    g_xnorm[n] = emu_hreduce(S);
}

// ---------------------------------------------------------------------------
// Argmin kernel. dist_ref = fl( fl(a_n + b_k) - fl(2*c) ), c accumulated as a
// single fp32 fma chain over ascending d (matches Eigen / cublas sgemm).
// Tie -> lowest code index (first occurrence, matches jnp.argmin).
// ---------------------------------------------------------------------------
#define TM 128
#define TN 128
#define TD 32
#define ES_PITCH 132
#define ARGMIN_SMEM ((D_DIM * TM + TD * ES_PITCH) * 4)

__global__ __launch_bounds__(256, 1) void vq_argmin(
    const float* __restrict__ x, const float* __restrict__ E) {
    extern __shared__ float smem[];
    float* xs = smem;                   // [D_DIM][TM]
    float* es = smem + D_DIM * TM;      // [TD][ES_PITCH]

    const int tid = threadIdx.x;
    const int ty = tid >> 4;            // query group (8 queries)
    const int tx = tid & 15;            // code group (8 codes)
    const int n0 = blockIdx.x * TM;
    const int b  = n0 >> 11;
    const int t0 = n0 & (T_DIM - 1);
    const float* xb = x + (size_t)b * D_DIM * T_DIM + t0;

#pragma unroll
    for (int r = 0; r < (D_DIM * TM / 4) / 256; r++) {
        int i4 = tid + r * 256;
        int d  = i4 >> 5;
        int t4 = (i4 & 31) << 2;
        float4 v = *(const float4*)(xb + (size_t)d * T_DIM + t4);
        *(float4*)&xs[d * TM + t4] = v;
    }

    float aq[8];
#pragma unroll
    for (int i = 0; i < 8; i++) aq[i] = g_xnorm[n0 + ty * 8 + i];

    float best[8];
    int   bidx[8];
#pragma unroll
    for (int i = 0; i < 8; i++) { best[i] = CUDART_INF_F; bidx[i] = 0; }

    for (int c0 = 0; c0 < K_CODES; c0 += TN) {
        float acc[8][8];
#pragma unroll
        for (int i = 0; i < 8; i++)
#pragma unroll
            for (int j = 0; j < 8; j++) acc[i][j] = 0.0f;

        for (int d0 = 0; d0 < D_DIM; d0 += TD) {
            __syncthreads();
#pragma unroll
            for (int r = 0; r < (TD * TN) / 256; r++) {
                int i  = tid + r * 256;
                int c  = i >> 5;
                int dd = i & 31;
                es[dd * ES_PITCH + c] = E[(size_t)(c0 + c) * D_DIM + d0 + dd];
            }
            __syncthreads();
#pragma unroll 8
            for (int d = 0; d < TD; d++) {
                const float* xr = &xs[(d0 + d) * TM + ty * 8];
                const float* er = &es[d * ES_PITCH + tx * 8];
                float4 a0 = *(const float4*)xr;
                float4 a1 = *(const float4*)(xr + 4);
                float4 b0 = *(const float4*)er;
                float4 b1 = *(const float4*)(er + 4);
                float av[8] = {a0.x, a0.y, a0.z, a0.w, a1.x, a1.y, a1.z, a1.w};
                float bv[8] = {b0.x, b0.y, b0.z, b0.w, b1.x, b1.y, b1.z, b1.w};
#pragma unroll
                for (int i = 0; i < 8; i++)
#pragma unroll
                    for (int j = 0; j < 8; j++)
                        acc[i][j] = fmaf(av[i], bv[j], acc[i][j]);
            }
        }
        // Fold with reference-exact fp32 elementwise emulation
#pragma unroll
        for (int j = 0; j < 8; j++) {
            int c = c0 + tx * 8 + j;
            float en = g_enorm[c];
#pragma unroll
            for (int i = 0; i < 8; i++) {
                float S    = __fadd_rn(aq[i], en);          // fl(a+b)
                float t2   = __fmul_rn(2.0f, acc[i][j]);    // fl(2c) (exact)
                float dist = __fsub_rn(S, t2);              // fl(S-2c)
                if (dist < best[i]) { best[i] = dist; bidx[i] = c; }
            }
        }
    }

    // Cross-lane reduce (16 tx lanes per query), ties -> lower index
#pragma unroll
    for (int o = 8; o; o >>= 1) {
#pragma unroll
        for (int i = 0; i < 8; i++) {
            float ov = __shfl_xor_sync(0xFFFFFFFFu, best[i], o);
            int   oi = __shfl_xor_sync(0xFFFFFFFFu, bidx[i], o);
            if (ov < best[i] || (ov == best[i] && oi < bidx[i])) {
                best[i] = ov; bidx[i] = oi;
            }
        }
    }
    if (tx == 0) {
#pragma unroll
        for (int i = 0; i < 8; i++) g_idx[n0 + ty * 8 + i] = bidx[i];
    }
}

// ---------------------------------------------------------------------------
// Deterministic segment-sum: fixed-point int64 atomics (order-independent)
// ---------------------------------------------------------------------------
__global__ void vq_scatter(const float* __restrict__ x) {
    int u = blockIdx.x * blockDim.x + threadIdx.x;
    if (u >= N_Q * D_DIM) return;
    int n = u & (N_Q - 1);
    int d = u >> 14;
    int k = g_idx[n];
    int b = n >> 11;
    int t = n & (T_DIM - 1);
    float v = x[((size_t)(b * D_DIM + d)) * T_DIM + t];
    long long fx = llrint((double)v * FIX_SCALE);
    atomicAdd(&g_dw[k * D_DIM + d], (unsigned long long)fx);
    if (d == 0) atomicAdd(&g_cnt[k], 1);
}

// ---------------------------------------------------------------------------
// Outputs 0..2: quantized = gather(E, idx) twice; vq_in_bdt = x
// ---------------------------------------------------------------------------
__global__ void vq_gather(const float* __restrict__ x, const float* __restrict__ E,
                          float* __restrict__ out) {
    int o = blockIdx.x * blockDim.x + threadIdx.x;
    if (o >= OUT_SEC) return;
    int t  = o & (T_DIM - 1);
    int bd = o >> 11;
    int d  = bd & (D_DIM - 1);
    int b  = bd >> 8;
    int n  = (b << 11) + t;
    int k  = g_idx[n];
    float v = __ldg(&E[(size_t)k * D_DIM + d]);
    out[o]               = v;        // quantized (STE == vq_out to fp32)
    out[o + 2 * OUT_SEC] = v;        // stop_gradient(quantized)
    out[o + OUT_SEC]     = x[o];     // vq_in_bdt == x
}

// ---------------------------------------------------------------------------
// n = sum(ema_cs) (fp64 reduce, then fp32 — deviation from ref < 1e-9 rel)
// ---------------------------------------------------------------------------
__global__ void vq_n() {
    __shared__ double sh[256];
    double s = 0.0;
    for (int k = threadIdx.x; k < K_CODES; k += 256) {
        float cs = (float)g_cnt[k];
        float e1 = __fmul_rn(cs, ONE_M_DECAY);
        float e2 = __fdiv_rn(e1, ONE_M_DECAY);
        s += (double)e2;
    }
    sh[threadIdx.x] = s;
    __syncthreads();
    for (int o = 128; o; o >>= 1) {
        if (threadIdx.x < o) sh[threadIdx.x] += sh[threadIdx.x + o];
        __syncthreads();
    }
    if (threadIdx.x == 0) g_nval = (float)sh[0];
}

// ---------------------------------------------------------------------------
// Output 3: new_embeddings with reference-exact fp32 elementwise ops
// ---------------------------------------------------------------------------
__global__ void vq_finalize(float* __restrict__ out3) {
    int i = blockIdx.x * blockDim.x + threadIdx.x;
    if (i >= K_CODES * D_DIM) return;
    int k = i >> 8;
    float n = g_nval;
    float cs = (float)g_cnt[k];
    float ema_cs = __fdiv_rn(__fmul_rn(cs, ONE_M_DECAY), ONE_M_DECAY);
    float dwf = (float)((double)(long long)g_dw[i] / FIX_SCALE);
    float ema_dw = __fdiv_rn(__fmul_rn(dwf, ONE_M_DECAY), ONE_M_DECAY);
    float keps  = __fmul_rn((float)K_CODES, EPS_F);
    float denom = __fadd_rn(n, keps);
    float tnum  = __fadd_rn(ema_cs, EPS_F);
    float u     = __fdiv_rn(tnum, denom);
    float v     = __fmul_rn(u, n);
    out3[i] = __fdiv_rn(ema_dw, v);
}

// ---------------------------------------------------------------------------
extern "C" void kernel_launch(void* const* d_in, const int* in_sizes, int n_in,
                              void* d_out, int out_size) {
    const float* x = (const float*)d_in[0];
    const float* E = (const float*)d_in[1];
    if (n_in >= 2 && in_sizes[0] == K_CODES * D_DIM && in_sizes[1] == OUT_SEC) {
        E = (const float*)d_in[0];
        x = (const float*)d_in[1];
    }
    float* out = (float*)d_out;

    vq_zero<<<2048, 256>>>();
    vq_bnorm<<<K_CODES / 256, 256>>>(E);
    vq_anorm<<<N_Q / 256, 256>>>(x);

    cudaFuncSetAttribute(vq_argmin, cudaFuncAttributeMaxDynamicSharedMemorySize,
                         ARGMIN_SMEM);
    vq_argmin<<<N_Q / TM, 256, ARGMIN_SMEM>>>(x, E);

    vq_scatter<<<(N_Q * D_DIM) / 256, 256>>>(x);
    vq_gather<<<OUT_SEC / 256, 256>>>(x, E, out);
    vq_n<<<1, 256>>>();
    vq_finalize<<<(K_CODES * D_DIM) / 256, 256>>>(out + 3 * (size_t)OUT_SEC);
}

// round 3
// speedup vs baseline: 1.3764x; 1.3764x over previous
#include <cuda_runtime.h>
#include <cuda_bf16.h>
#include <math_constants.h>
#include <cstdint>
#include <cstddef>

// Problem constants (fixed shapes from reference)
#define K_CODES 8192
#define D_DIM   256
#define T_DIM   2048
#define B_DIM   8
#define N_Q     (B_DIM * T_DIM)          /* 16384 */
#define OUT_SEC (B_DIM * D_DIM * T_DIM)  /* 4194304 */
#define N_T16   (K_CODES / 16)           /* 512 tile-mins per query */

#define ONE_M_DECAY 0.009999999776482582092285156250f
#define EPS_F 1e-5f
#define FIX_SCALE 4294967296.0
#define MARGIN 0.16f

// Device scratch (no allocations allowed)
__device__ float              g_enorm[K_CODES];
__device__ float              g_xnorm[N_Q];
__device__ int                g_idx[N_Q];
__device__ int                g_cnt[K_CODES];
__device__ unsigned long long g_dw[K_CODES * D_DIM];
__device__ float              g_nval;
__device__ __nv_bfloat16      g_xb[N_Q * D_DIM];      // x transposed [n][d], bf16
__device__ __nv_bfloat16      g_eb[K_CODES * D_DIM];  // E bf16
__device__ float              g_tilemin[(size_t)N_Q * N_T16];

// ---------------------------------------------------------------------------
__global__ void vq_zero() {
    int i = blockIdx.x * blockDim.x + threadIdx.x;
    int stride = gridDim.x * blockDim.x;
    for (int j = i; j < K_CODES * D_DIM; j += stride) g_dw[j] = 0ull;
    for (int j = i; j < K_CODES; j += stride) g_cnt[j] = 0;
}

// ---------------------------------------------------------------------------
// Emulated XLA fp32 squared-norm reduce (8 strided lanes, mul-then-add)
// ---------------------------------------------------------------------------
__device__ __forceinline__ float emu_hreduce(const float S[8]) {
    float t1 = __fadd_rn(S[0], S[4]);
    float t2 = __fadd_rn(S[2], S[6]);
    float t3 = __fadd_rn(S[1], S[5]);
    float t4 = __fadd_rn(S[3], S[7]);
    return __fadd_rn(__fadd_rn(t1, t2), __fadd_rn(t3, t4));
}

__global__ void vq_bnorm(const float* __restrict__ E) {
    int k = blockIdx.x * blockDim.x + threadIdx.x;
    if (k >= K_CODES) return;
    const float* row = E + (size_t)k * D_DIM;
    float S[8];
#pragma unroll
    for (int j = 0; j < 8; j++) S[j] = 0.0f;
#pragma unroll 4
    for (int i = 0; i < D_DIM / 8; i++)
#pragma unroll
        for (int j = 0; j < 8; j++) {
            float v = row[i * 8 + j];
            S[j] = __fadd_rn(S[j], __fmul_rn(v, v));
        }
    g_enorm[k] = emu_hreduce(S);
}

__global__ void vq_anorm(const float* __restrict__ x) {
    int n = blockIdx.x * blockDim.x + threadIdx.x;
    if (n >= N_Q) return;
    int b = n >> 11;
    int t = n & (T_DIM - 1);
    const float* xb = x + (size_t)b * D_DIM * T_DIM + t;
    float S[8];
#pragma unroll
    for (int j = 0; j < 8; j++) S[j] = 0.0f;
#pragma unroll 4
    for (int i = 0; i < D_DIM / 8; i++)
#pragma unroll
        for (int j = 0; j < 8; j++) {
            float v = xb[(size_t)(i * 8 + j) * T_DIM];
            S[j] = __fadd_rn(S[j], __fmul_rn(v, v));
        }
    g_xnorm[n] = emu_hreduce(S);
}

// ---------------------------------------------------------------------------
// bf16 prep: E elementwise; x transposed [b][d][t] -> [n][d] via smem tiles
// ---------------------------------------------------------------------------
__global__ void vq_ebf16(const float* __restrict__ E) {
    int i = blockIdx.x * blockDim.x + threadIdx.x;
    if (i < K_CODES * D_DIM) g_eb[i] = __float2bfloat16(E[i]);
}

__global__ void vq_xbf16(const float* __restrict__ x) {
    __shared__ float tile[32][33];
    int b  = blockIdx.z;
    int d0 = blockIdx.y * 32;
    int t0 = blockIdx.x * 32;
    int tx = threadIdx.x, ty = threadIdx.y;   // 32 x 8
#pragma unroll
    for (int i = 0; i < 4; i++) {
        int d = d0 + ty + i * 8;
        tile[ty + i * 8][tx] = x[((size_t)(b * D_DIM + d)) * T_DIM + t0 + tx];
    }
    __syncthreads();
#pragma unroll
    for (int i = 0; i < 4; i++) {
        int t = t0 + ty + i * 8;
        int n = b * T_DIM + t;
        g_xb[(size_t)n * D_DIM + d0 + tx] = __float2bfloat16(tile[tx][ty + i * 8]);
    }
}

// ---------------------------------------------------------------------------
// Tensor-core approx sweep: block tile 128q x 256c, 8 warps (warp 64x64),
// bf16 m16n8k16 mma, K=256 in chunks of 32 (cp.async double buffer).
// Writes per-(query, 16-code tile) min of s = enorm - 2*dot.
// ---------------------------------------------------------------------------
#define QB 128
#define CB 256
#define KC 32
#define XP 40    /* smem row pitch (bf16) to de-conflict ldmatrix */
#define EP 40
#define XS_ELE (QB * XP)
#define ES_ELE (CB * EP)
#define MMA_SMEM ((XS_ELE + ES_ELE) * 2 * 2)  /* 2 buffers, 2B each = 61440 */

__device__ __forceinline__ void cp16(uint32_t s, const void* g) {
    asm volatile("cp.async.cg.shared.global [%0], [%1], 16;\n"
                 :: "r"(s), "l"(g) : "memory");
}
__device__ __forceinline__ void cp_commit() {
    asm volatile("cp.async.commit_group;\n" ::: "memory");
}
__device__ __forceinline__ void ldmx4(uint32_t addr, uint32_t& r0, uint32_t& r1,
                                      uint32_t& r2, uint32_t& r3) {
    asm volatile("ldmatrix.sync.aligned.m8n8.x4.shared.b16 {%0,%1,%2,%3},[%4];\n"
                 : "=r"(r0), "=r"(r1), "=r"(r2), "=r"(r3) : "r"(addr));
}

__global__ __launch_bounds__(256, 1) void vq_mma() {
    extern __shared__ __align__(16) __nv_bfloat16 sm[];
    const uint32_t sbase = (uint32_t)__cvta_generic_to_shared(sm);
    const uint32_t xs_off[2] = {sbase, sbase + XS_ELE * 2};
    const uint32_t es_off[2] = {sbase + 2 * XS_ELE * 2,
                                sbase + 2 * XS_ELE * 2 + ES_ELE * 2};

    const int tid  = threadIdx.x;
    const int warp = tid >> 5;
    const int lane = tid & 31;
    const int qb = blockIdx.x * QB;
    const int cb = blockIdx.y * CB;
    const int wq = (warp >> 2) * 64;
    const int wc = (warp & 3) * 64;

    float acc[4][8][4];
#pragma unroll
    for (int mt = 0; mt < 4; mt++)
#pragma unroll
        for (int nt = 0; nt < 8; nt++)
#pragma unroll
            for (int j = 0; j < 4; j++) acc[mt][nt][j] = 0.0f;

    // chunk loader: 512 x-granules + 1024 e-granules of 16B
    auto load_chunk = [&](int ch, int buf) {
        int k0 = ch * KC;
#pragma unroll
        for (int r = 0; r < 2; r++) {
            int g = tid + r * 256;
            int row = g >> 2, cg = g & 3;
            cp16(xs_off[buf] + (uint32_t)(row * XP + cg * 8) * 2,
                 &g_xb[(size_t)(qb + row) * D_DIM + k0 + cg * 8]);
        }
#pragma unroll
        for (int r = 0; r < 4; r++) {
            int g = tid + r * 256;
            int row = g >> 2, cg = g & 3;
            cp16(es_off[buf] + (uint32_t)(row * EP + cg * 8) * 2,
                 &g_eb[(size_t)(cb + row) * D_DIM + k0 + cg * 8]);
        }
        cp_commit();
    };

    load_chunk(0, 0);
    load_chunk(1, 1);

    const int NCH = D_DIM / KC;  // 8
    for (int ch = 0; ch < NCH; ch++) {
        int buf = ch & 1;
        if (ch < NCH - 1)
            asm volatile("cp.async.wait_group 1;\n" ::: "memory");
        else
            asm volatile("cp.async.wait_group 0;\n" ::: "memory");
        __syncthreads();

#pragma unroll
        for (int ks = 0; ks < 2; ks++) {
            const int kk = ks * 16;
            uint32_t a[4][4];
            uint32_t bb[8][2];
#pragma unroll
            for (int mt = 0; mt < 4; mt++) {
                uint32_t addr = xs_off[buf] +
                    (uint32_t)((wq + mt * 16 + (lane & 15)) * XP +
                               kk + ((lane >> 4) * 8)) * 2;
                ldmx4(addr, a[mt][0], a[mt][1], a[mt][2], a[mt][3]);
            }
#pragma unroll
            for (int np = 0; np < 4; np++) {
                int row  = np * 16 + (lane & 7) + (((lane >> 4) & 1) * 8);
                int kcol = kk + (((lane >> 3) & 1) * 8);
                uint32_t addr = es_off[buf] +
                    (uint32_t)((wc + row) * EP + kcol) * 2;
                ldmx4(addr, bb[2 * np][0], bb[2 * np][1],
                      bb[2 * np + 1][0], bb[2 * np + 1][1]);
            }
#pragma unroll
            for (int mt = 0; mt < 4; mt++)
#pragma unroll
                for (int nt = 0; nt < 8; nt++) {
                    asm volatile(
                        "mma.sync.aligned.m16n8k16.row.col.f32.bf16.bf16.f32 "
                        "{%0,%1,%2,%3},{%4,%5,%6,%7},{%8,%9},{%0,%1,%2,%3};\n"
                        : "+f"(acc[mt][nt][0]), "+f"(acc[mt][nt][1]),
                          "+f"(acc[mt][nt][2]), "+f"(acc[mt][nt][3])
                        : "r"(a[mt][0]), "r"(a[mt][1]),
                          "r"(a[mt][2]), "r"(a[mt][3]),
                          "r"(bb[nt][0]), "r"(bb[nt][1]));
                }
        }
        __syncthreads();
        if (ch + 2 < NCH) load_chunk(ch + 2, buf);
    }

    // Epilogue: s = en - 2*acc; per-16-code tile-min, reduce across lane&3
    const int cpair = (lane & 3) * 2;
    float en[8][2];
#pragma unroll
    for (int nt = 0; nt < 8; nt++) {
        int c = cb + wc + nt * 8 + cpair;
        en[nt][0] = g_enorm[c];
        en[nt][1] = g_enorm[c + 1];
    }
#pragma unroll
    for (int mt = 0; mt < 4; mt++) {
        float vlo[4], vhi[4];
#pragma unroll
        for (int tj = 0; tj < 4; tj++) { vlo[tj] = CUDART_INF_F; vhi[tj] = CUDART_INF_F; }
#pragma unroll
        for (int nt = 0; nt < 8; nt++) {
            float s0 = fmaf(-2.0f, acc[mt][nt][0], en[nt][0]);
            float s1 = fmaf(-2.0f, acc[mt][nt][1], en[nt][1]);
            float s2 = fmaf(-2.0f, acc[mt][nt][2], en[nt][0]);
            float s3 = fmaf(-2.0f, acc[mt][nt][3], en[nt][1]);
            int tj = nt >> 1;
            vlo[tj] = fminf(vlo[tj], fminf(s0, s1));
            vhi[tj] = fminf(vhi[tj], fminf(s2, s3));
        }
#pragma unroll
        for (int tj = 0; tj < 4; tj++) {
#pragma unroll
            for (int off = 1; off < 4; off <<= 1) {
                vlo[tj] = fminf(vlo[tj], __shfl_xor_sync(0xFFFFFFFFu, vlo[tj], off));
                vhi[tj] = fminf(vhi[tj], __shfl_xor_sync(0xFFFFFFFFu, vhi[tj], off));
            }
        }
        if ((lane & 3) == 0) {
            int q  = qb + wq + mt * 16 + (lane >> 2);
            int tb = (cb + wc) >> 4;
#pragma unroll
            for (int tj = 0; tj < 4; tj++) {
                g_tilemin[(size_t)q * N_T16 + tb + tj]       = vlo[tj];
                g_tilemin[(size_t)(q + 8) * N_T16 + tb + tj] = vhi[tj];
            }
        }
    }
}

// ---------------------------------------------------------------------------
// Exact rescore: one warp per query; visit tiles with tm <= gm + MARGIN,
// sequential ascending-d fp32 fma chain (bit-matches reference), lowest-index
// tie-break. Writes g_idx.
// ---------------------------------------------------------------------------
__global__ __launch_bounds__(256) void vq_rescore(
    const float* __restrict__ x, const float* __restrict__ E) {
    __shared__ float xrow[8][D_DIM];
    const int warp = threadIdx.x >> 5;
    const int lane = threadIdx.x & 31;
    const int q = blockIdx.x * 8 + warp;

    // Load this query's x row into smem
    {
        int b = q >> 11, t = q & (T_DIM - 1);
#pragma unroll
        for (int i = 0; i < D_DIM / 32; i++) {
            int d = lane + i * 32;
            xrow[warp][d] = x[((size_t)(b * D_DIM + d)) * T_DIM + t];
        }
    }
    __syncwarp();

    const float* tm = &g_tilemin[(size_t)q * N_T16];
    float gm = CUDART_INF_F;
#pragma unroll
    for (int j = 0; j < N_T16 / 32; j++)
        gm = fminf(gm, tm[j * 32 + lane]);
#pragma unroll
    for (int off = 16; off; off >>= 1)
        gm = fminf(gm, __shfl_xor_sync(0xFFFFFFFFu, gm, off));
    const float thr = gm + MARGIN;
    const float a = g_xnorm[q];

    float best = CUDART_INF_F;
    int   bidx = 0x7FFFFFFF;

    for (int j = 0; j < N_T16 / 32; j++) {
        float v = tm[j * 32 + lane];
        unsigned m = __ballot_sync(0xFFFFFFFFu, v <= thr);
        while (m) {
            int bpos = __ffs(m) - 1;
            m &= m - 1;
            int tile = j * 32 + bpos;
            int c = tile * 16 + lane;        // lanes 0-15 active
            float dist = CUDART_INF_F;
            int   ci   = 0x7FFFFFFF;
            if (lane < 16) {
                const float* er = E + (size_t)c * D_DIM;
                const float* xr = xrow[warp];
                float acc = 0.0f;
#pragma unroll 8
                for (int d = 0; d < D_DIM; d++)
                    acc = fmaf(xr[d], er[d], acc);
                float S  = __fadd_rn(a, g_enorm[c]);
                float t2 = __fmul_rn(2.0f, acc);
                dist = __fsub_rn(S, t2);
                ci = c;
            }
            // warp argmin with lowest-index tiebreak
#pragma unroll
            for (int off = 16; off; off >>= 1) {
                float ov = __shfl_xor_sync(0xFFFFFFFFu, dist, off);
                int   oi = __shfl_xor_sync(0xFFFFFFFFu, ci, off);
                if (ov < dist || (ov == dist && oi < ci)) { dist = ov; ci = oi; }
            }
            if (dist < best || (dist == best && ci < bidx)) { best = dist; bidx = ci; }
        }
    }
    if (lane == 0) g_idx[q] = bidx;
}

// ---------------------------------------------------------------------------
// Deterministic segment-sum (fixed-point), gather outputs, EMA finalize
// ---------------------------------------------------------------------------
__global__ void vq_scatter(const float* __restrict__ x) {
    int u = blockIdx.x * blockDim.x + threadIdx.x;
    if (u >= N_Q * D_DIM) return;
    int n = u & (N_Q - 1);
    int d = u >> 14;
    int k = g_idx[n];
    int b = n >> 11;
    int t = n & (T_DIM - 1);
    float v = x[((size_t)(b * D_DIM + d)) * T_DIM + t];
    long long fx = llrint((double)v * FIX_SCALE);
    atomicAdd(&g_dw[k * D_DIM + d], (unsigned long long)fx);
    if (d == 0) atomicAdd(&g_cnt[k], 1);
}

__global__ void vq_gather(const float* __restrict__ x, const float* __restrict__ E,
                          float* __restrict__ out) {
    int o = blockIdx.x * blockDim.x + threadIdx.x;
    if (o >= OUT_SEC) return;
    int t  = o & (T_DIM - 1);
    int bd = o >> 11;
    int d  = bd & (D_DIM - 1);
    int b  = bd >> 8;
    int n  = (b << 11) + t;
    int k  = g_idx[n];
    float v = __ldg(&E[(size_t)k * D_DIM + d]);
    out[o]               = v;
    out[o + 2 * OUT_SEC] = v;
    out[o + OUT_SEC]     = x[o];
}

__global__ void vq_n() {
    __shared__ double sh[256];
    double s = 0.0;
    for (int k = threadIdx.x; k < K_CODES; k += 256) {
        float cs = (float)g_cnt[k];
        float e1 = __fmul_rn(cs, ONE_M_DECAY);
        float e2 = __fdiv_rn(e1, ONE_M_DECAY);
        s += (double)e2;
    }
    sh[threadIdx.x] = s;
    __syncthreads();
    for (int o = 128; o; o >>= 1) {
        if (threadIdx.x < o) sh[threadIdx.x] += sh[threadIdx.x + o];
        __syncthreads();
    }
    if (threadIdx.x == 0) g_nval = (float)sh[0];
}

__global__ void vq_finalize(float* __restrict__ out3) {
    int i = blockIdx.x * blockDim.x + threadIdx.x;
    if (i >= K_CODES * D_DIM) return;
    int k = i >> 8;
    float n = g_nval;
    float cs = (float)g_cnt[k];
    float ema_cs = __fdiv_rn(__fmul_rn(cs, ONE_M_DECAY), ONE_M_DECAY);
    float dwf = (float)((double)(long long)g_dw[i] / FIX_SCALE);
    float ema_dw = __fdiv_rn(__fmul_rn(dwf, ONE_M_DECAY), ONE_M_DECAY);
    float keps  = __fmul_rn((float)K_CODES, EPS_F);
    float denom = __fadd_rn(n, keps);
    float tnum  = __fadd_rn(ema_cs, EPS_F);
    float u     = __fdiv_rn(tnum, denom);
    float v     = __fmul_rn(u, n);
    out3[i] = __fdiv_rn(ema_dw, v);
}

// ---------------------------------------------------------------------------
extern "C" void kernel_launch(void* const* d_in, const int* in_sizes, int n_in,
                              void* d_out, int out_size) {
    const float* x = (const float*)d_in[0];
    const float* E = (const float*)d_in[1];
    if (n_in >= 2 && in_sizes[0] == K_CODES * D_DIM && in_sizes[1] == OUT_SEC) {
        E = (const float*)d_in[0];
        x = (const float*)d_in[1];
    }
    float* out = (float*)d_out;

    vq_zero<<<2048, 256>>>();
    vq_bnorm<<<K_CODES / 256, 256>>>(E);
    vq_anorm<<<N_Q / 256, 256>>>(x);
    vq_ebf16<<<(K_CODES * D_DIM) / 256, 256>>>(E);
    {
        dim3 g(T_DIM / 32, D_DIM / 32, B_DIM);
        dim3 b(32, 8);
        vq_xbf16<<<g, b>>>(x);
    }

    cudaFuncSetAttribute(vq_mma, cudaFuncAttributeMaxDynamicSharedMemorySize,
                         MMA_SMEM);
    {
        dim3 g(N_Q / QB, K_CODES / CB);   // 128 x 32
        vq_mma<<<g, 256, MMA_SMEM>>>();
    }
    vq_rescore<<<N_Q / 8, 256>>>(x, E);

    vq_scatter<<<(N_Q * D_DIM) / 256, 256>>>(x);
    vq_gather<<<OUT_SEC / 256, 256>>>(x, E, out);
    vq_n<<<1, 256>>>();
    vq_finalize<<<(K_CODES * D_DIM) / 256, 256>>>(out + 3 * (size_t)OUT_SEC);
}